// round 1
// baseline (speedup 1.0000x reference)
#include <cuda_runtime.h>

#define NMAX 100000
#define EMAX 1600000
#define CH 128

// ---------------- scratch (device globals; no allocations allowed) ----------
__device__ float g_deg[NMAX];
__device__ float g_dinv[NMAX];
__device__ int   g_cnt[NMAX];
__device__ int   g_off[NMAX + 1];
__device__ int   g_pos[NMAX];
__device__ int   g_eidx[EMAX];
__device__ float g_ecoef[EMAX];
__device__ float g_bufA[(size_t)NMAX * CH];
__device__ float g_bufB[(size_t)NMAX * CH];

// ---------------- graph preprocessing ---------------------------------------

__global__ void init_kernel(int n) {
    int i = blockIdx.x * blockDim.x + threadIdx.x;
    if (i < n) {
        g_deg[i] = 1.0f;   // self-loop weight 1
        g_cnt[i] = 0;
    }
}

__global__ void deg_cnt_kernel(const int* __restrict__ row,
                               const int* __restrict__ col,
                               const float* __restrict__ ew, int E) {
    int e = blockIdx.x * blockDim.x + threadIdx.x;
    if (e < E) {
        int c = col[e];
        atomicAdd(&g_deg[c], ew[e]);
        atomicAdd(&g_cnt[c], 1);
    }
}

__global__ void dinv_kernel(int n) {
    int i = blockIdx.x * blockDim.x + threadIdx.x;
    if (i < n) {
        float d = g_deg[i];
        g_dinv[i] = (d > 0.0f) ? rsqrtf(d) : 0.0f;
    }
}

// single-block exclusive scan of g_cnt -> g_off (and g_pos copy)
__global__ void scan_kernel(int n) {
    __shared__ int warp_sums[32];
    __shared__ int s_carry;
    int tid = threadIdx.x;
    if (tid == 0) s_carry = 0;
    __syncthreads();
    for (int base = 0; base < n; base += 1024) {
        int i = base + tid;
        int v = (i < n) ? g_cnt[i] : 0;
        // inclusive warp scan
        int x = v;
        #pragma unroll
        for (int d = 1; d < 32; d <<= 1) {
            int y = __shfl_up_sync(0xffffffffu, x, d);
            if ((tid & 31) >= d) x += y;
        }
        if ((tid & 31) == 31) warp_sums[tid >> 5] = x;
        __syncthreads();
        if (tid < 32) {
            int w = warp_sums[tid];
            int xs = w;
            #pragma unroll
            for (int d = 1; d < 32; d <<= 1) {
                int y = __shfl_up_sync(0xffffffffu, xs, d);
                if (tid >= d) xs += y;
            }
            warp_sums[tid] = xs - w;   // exclusive warp offsets
        }
        __syncthreads();
        int incl = x + warp_sums[tid >> 5];
        int excl = incl - v + s_carry;
        if (i < n) { g_off[i] = excl; g_pos[i] = excl; }
        __syncthreads();
        if (tid == 1023) s_carry += incl;   // last thread's inclusive == chunk total
        __syncthreads();
    }
    if (tid == 0) g_off[n] = s_carry;
}

__global__ void fill_kernel(const int* __restrict__ row,
                            const int* __restrict__ col,
                            const float* __restrict__ ew, int E) {
    int e = blockIdx.x * blockDim.x + threadIdx.x;
    if (e < E) {
        int r = row[e], c = col[e];
        int p = atomicAdd(&g_pos[c], 1);
        g_eidx[p] = r;
        g_ecoef[p] = g_dinv[r] * ew[e] * g_dinv[c];
    }
}

// ---------------- GEMM: C[M,128] = A[M,128] @ W[128,128] ---------------------
// BM=128, BN=128, BK=8, 256 threads, 8x8 per thread.
// src_sel: 0 = external A pointer, 1 = g_bufA, 2 = g_bufB
// dst_sel: 1 = g_bufA, 2 = g_bufB

__global__ void __launch_bounds__(256)
gemm_kernel(const float* __restrict__ Aext, int src_sel, int dst_sel,
            const float* __restrict__ W, int M) {
    const float* A = (src_sel == 0) ? Aext : (src_sel == 1 ? g_bufA : g_bufB);
    float* Cout = (dst_sel == 1) ? g_bufA : g_bufB;

    __shared__ float As[8][128];
    __shared__ float Bs[8][128];

    int tid = threadIdx.x;
    int tx = tid & 15;         // 0..15 -> N
    int ty = tid >> 4;         // 0..15 -> M
    int block_row = blockIdx.x * 128;

    float acc[8][8];
    #pragma unroll
    for (int m = 0; m < 8; m++)
        #pragma unroll
        for (int nn = 0; nn < 8; nn++) acc[m][nn] = 0.0f;

    int a_row = tid >> 1;            // 0..127
    int a_col = (tid & 1) * 4;       // 0 or 4
    int b_row = tid >> 5;            // 0..7
    int b_col = (tid & 31) * 4;      // 0..124

    for (int k0 = 0; k0 < 128; k0 += 8) {
        int gr = block_row + a_row;
        float4 av = make_float4(0.f, 0.f, 0.f, 0.f);
        if (gr < M) av = *(const float4*)(A + (size_t)gr * 128 + k0 + a_col);
        As[a_col + 0][a_row] = av.x;
        As[a_col + 1][a_row] = av.y;
        As[a_col + 2][a_row] = av.z;
        As[a_col + 3][a_row] = av.w;
        float4 bv = *(const float4*)(W + (size_t)(k0 + b_row) * 128 + b_col);
        *(float4*)&Bs[b_row][b_col] = bv;
        __syncthreads();

        #pragma unroll
        for (int k = 0; k < 8; k++) {
            float rm[8], rn[8];
            #pragma unroll
            for (int m = 0; m < 8; m++) rm[m] = As[k][ty * 8 + m];
            #pragma unroll
            for (int nn = 0; nn < 8; nn++) rn[nn] = Bs[k][tx * 8 + nn];
            #pragma unroll
            for (int m = 0; m < 8; m++)
                #pragma unroll
                for (int nn = 0; nn < 8; nn++)
                    acc[m][nn] = fmaf(rm[m], rn[nn], acc[m][nn]);
        }
        __syncthreads();
    }

    #pragma unroll
    for (int m = 0; m < 8; m++) {
        int gr = block_row + ty * 8 + m;
        if (gr < M) {
            float* cp = Cout + (size_t)gr * 128 + tx * 8;
            *(float4*)(cp + 0) = make_float4(acc[m][0], acc[m][1], acc[m][2], acc[m][3]);
            *(float4*)(cp + 4) = make_float4(acc[m][4], acc[m][5], acc[m][6], acc[m][7]);
        }
    }
}

// ---------------- Aggregation: out[i] = sum coef*xw[nbr] + dinv[i]^2*xw[i] + b
// warp per node; lane owns 4 channels (float4).
// src_sel: 1 = g_bufA, 2 = g_bufB.  dst: external pointer (out) always.

__global__ void __launch_bounds__(256)
agg_kernel(int src_sel, const float* __restrict__ bias,
           float* __restrict__ out, int n, int do_relu) {
    const float* xw = (src_sel == 1) ? g_bufA : g_bufB;
    int warp = (blockIdx.x * blockDim.x + threadIdx.x) >> 5;
    int lane = threadIdx.x & 31;
    if (warp >= n) return;
    int i = warp;

    const float4* xw4 = (const float4*)xw;
    float4 b4 = ((const float4*)bias)[lane];
    float di = g_dinv[i];
    float sc = di * di;

    float4 self = __ldg(&xw4[(size_t)i * 32 + lane]);
    float4 acc = make_float4(self.x * sc, self.y * sc, self.z * sc, self.w * sc);

    int s = g_off[i], e = g_off[i + 1];
    for (int j0 = s; j0 < e; j0 += 32) {
        int j = j0 + lane;
        int idx = 0;
        float cf = 0.0f;
        if (j < e) { idx = g_eidx[j]; cf = g_ecoef[j]; }
        int m = min(32, e - j0);
        #pragma unroll 4
        for (int t = 0; t < m; ++t) {
            int r = __shfl_sync(0xffffffffu, idx, t);
            float c = __shfl_sync(0xffffffffu, cf, t);
            float4 v = __ldg(&xw4[(size_t)r * 32 + lane]);
            acc.x = fmaf(c, v.x, acc.x);
            acc.y = fmaf(c, v.y, acc.y);
            acc.z = fmaf(c, v.z, acc.z);
            acc.w = fmaf(c, v.w, acc.w);
        }
    }

    acc.x += b4.x; acc.y += b4.y; acc.z += b4.z; acc.w += b4.w;
    if (do_relu) {
        acc.x = fmaxf(acc.x, 0.0f);
        acc.y = fmaxf(acc.y, 0.0f);
        acc.z = fmaxf(acc.z, 0.0f);
        acc.w = fmaxf(acc.w, 0.0f);
    }
    ((float4*)out)[(size_t)i * 32 + lane] = acc;
}

// ---------------- launch ------------------------------------------------------

extern "C" void kernel_launch(void* const* d_in, const int* in_sizes, int n_in,
                              void* d_out, int out_size) {
    const float* x   = (const float*)d_in[0];
    const int*   ei  = (const int*)d_in[1];
    const float* ew  = (const float*)d_in[2];
    const float* W1  = (const float*)d_in[3];
    const float* b1  = (const float*)d_in[4];
    const float* W2  = (const float*)d_in[5];
    const float* b2  = (const float*)d_in[6];
    const float* W3  = (const float*)d_in[7];
    const float* b3  = (const float*)d_in[8];
    float* out = (float*)d_out;

    int n = in_sizes[0] / CH;        // 100000
    int E = in_sizes[2];             // 1600000
    const int* row = ei;
    const int* col = ei + E;

    // scratch pointers for agg output staging
    float* bufA = nullptr;
    float* bufB = nullptr;
    cudaGetSymbolAddress((void**)&bufA, g_bufA);
    cudaGetSymbolAddress((void**)&bufB, g_bufB);

    int tb = 256;
    int gn = (n + tb - 1) / tb;
    int ge = (E + tb - 1) / tb;
    int g_gemm = (n + 127) / 128;
    int g_agg = (n * 32 + tb - 1) / tb;

    // preprocessing: degrees, dinv, CSR by destination
    init_kernel<<<gn, tb>>>(n);
    deg_cnt_kernel<<<ge, tb>>>(row, col, ew, E);
    dinv_kernel<<<gn, tb>>>(n);
    scan_kernel<<<1, 1024>>>(n);
    fill_kernel<<<ge, tb>>>(row, col, ew, E);

    // layer 1: bufA = x@W1 ; bufB = relu(Agg(bufA)+b1)
    gemm_kernel<<<g_gemm, tb>>>(x, 0, 1, W1, n);
    agg_kernel<<<g_agg, tb>>>(1, b1, bufB, n, 1);

    // layer 2: bufA = bufB@W2 ; bufB = relu(Agg(bufA)+b2)  (stage via bufB? use distinct)
    gemm_kernel<<<g_gemm, tb>>>(nullptr, 2, 1, W2, n);
    agg_kernel<<<g_agg, tb>>>(1, b2, bufB, n, 1);

    // layer 3: bufA = bufB@W3 ; out = Agg(bufA)+b3
    gemm_kernel<<<g_gemm, tb>>>(nullptr, 2, 1, W3, n);
    agg_kernel<<<g_agg, tb>>>(1, b3, out, n, 0);
}

// round 5
// speedup vs baseline: 1.1504x; 1.1504x over previous
#include <cuda_runtime.h>

#define NMAX 100000
#define EMAX 1600000
#define CH 128
#define NBLK ((NMAX + 1023) / 1024)   // 98

// ---------------- scratch (device globals; no allocations allowed) ----------
__device__ float g_deg[NMAX];
__device__ float g_dinv[NMAX];
__device__ int   g_cnt[NMAX];
__device__ int   g_off[NMAX + 1];
__device__ int   g_pos[NMAX];
__device__ int   g_bsum[128];
__device__ int   g_boff[128];
__device__ int   g_eidx[EMAX];
__device__ float g_ecoef[EMAX];
__device__ float g_bufA[(size_t)NMAX * CH];
__device__ float g_bufB[(size_t)NMAX * CH];

// ---------------- packed f32x2 helpers ---------------------------------------

__device__ __forceinline__ unsigned long long pack2(float v) {
    unsigned long long r;
    unsigned int u = __float_as_uint(v);
    asm("mov.b64 %0, {%1, %1};" : "=l"(r) : "r"(u));
    return r;
}

__device__ __forceinline__ void ffma2(unsigned long long& d,
                                      unsigned long long a,
                                      unsigned long long b) {
    asm("fma.rn.f32x2 %0, %1, %2, %0;" : "+l"(d) : "l"(a), "l"(b));
}

// ---------------- graph preprocessing ---------------------------------------

__global__ void init_kernel(int n) {
    int i = blockIdx.x * blockDim.x + threadIdx.x;
    if (i < n) {
        g_deg[i] = 1.0f;   // self-loop weight 1
        g_cnt[i] = 0;
    }
}

__global__ void deg_cnt_kernel(const int* __restrict__ row,
                               const int* __restrict__ col,
                               const float* __restrict__ ew, int E) {
    int e = blockIdx.x * blockDim.x + threadIdx.x;
    if (e < E) {
        int c = col[e];
        atomicAdd(&g_deg[c], ew[e]);
        atomicAdd(&g_cnt[c], 1);
    }
}

// phase 1: per-block sums of g_cnt (1024 elems per block)
__global__ void __launch_bounds__(1024)
block_sum_kernel(int n) {
    __shared__ int wred[32];
    int i = blockIdx.x * 1024 + threadIdx.x;
    int v = (i < n) ? g_cnt[i] : 0;
    #pragma unroll
    for (int d = 16; d; d >>= 1) v += __shfl_down_sync(0xffffffffu, v, d);
    if ((threadIdx.x & 31) == 0) wred[threadIdx.x >> 5] = v;
    __syncthreads();
    if (threadIdx.x < 32) {
        int s = wred[threadIdx.x];
        #pragma unroll
        for (int d = 16; d; d >>= 1) s += __shfl_down_sync(0xffffffffu, s, d);
        if (threadIdx.x == 0) g_bsum[blockIdx.x] = s;
    }
}

// phase 2: exclusive scan of the 98 block sums (single warp, chunked)
__global__ void scan_bsum_kernel(int nb, int n) {
    int lane = threadIdx.x;
    int carry = 0;
    for (int base = 0; base < nb; base += 32) {
        int i = base + lane;
        int v = (i < nb) ? g_bsum[i] : 0;
        int x = v;
        #pragma unroll
        for (int d = 1; d < 32; d <<= 1) {
            int y = __shfl_up_sync(0xffffffffu, x, d);
            if (lane >= d) x += y;
        }
        if (i < nb) g_boff[i] = x - v + carry;
        int tot = __shfl_sync(0xffffffffu, x, 31);
        carry += tot;
    }
    if (lane == 0) g_off[n] = carry;
}

// phase 3: block-local exclusive scan + block offset; also compute dinv
__global__ void __launch_bounds__(1024)
scan_final_kernel(int n) {
    __shared__ int wsum[32];
    int tid = threadIdx.x;
    int lane = tid & 31, wid = tid >> 5;
    int i = blockIdx.x * 1024 + tid;
    int v = (i < n) ? g_cnt[i] : 0;
    int x = v;
    #pragma unroll
    for (int d = 1; d < 32; d <<= 1) {
        int y = __shfl_up_sync(0xffffffffu, x, d);
        if (lane >= d) x += y;
    }
    if (lane == 31) wsum[wid] = x;
    __syncthreads();
    if (tid < 32) {
        int w = wsum[tid];
        int xs = w;
        #pragma unroll
        for (int d = 1; d < 32; d <<= 1) {
            int y = __shfl_up_sync(0xffffffffu, xs, d);
            if (tid >= d) xs += y;
        }
        wsum[tid] = xs - w;   // exclusive warp offsets
    }
    __syncthreads();
    if (i < n) {
        int excl = x - v + wsum[wid] + g_boff[blockIdx.x];
        g_off[i] = excl;
        g_pos[i] = excl;
        float dg = g_deg[i];
        g_dinv[i] = (dg > 0.0f) ? rsqrtf(dg) : 0.0f;
    }
}

__global__ void fill_kernel(const int* __restrict__ row,
                            const int* __restrict__ col,
                            const float* __restrict__ ew, int E) {
    int e = blockIdx.x * blockDim.x + threadIdx.x;
    if (e < E) {
        int r = row[e], c = col[e];
        int p = atomicAdd(&g_pos[c], 1);
        g_eidx[p] = r;
        g_ecoef[p] = g_dinv[r] * ew[e] * g_dinv[c];
    }
}

// ---------------- GEMM: C[M,128] = A[M,128] @ W[128,128] ---------------------
// BM=128, BN=128, BK=8, 256 threads, 8x8 per thread; packed f32x2 FMAs.

__global__ void __launch_bounds__(256)
gemm_kernel(const float* __restrict__ Aext, int src_sel, int dst_sel,
            const float* __restrict__ W, int M) {
    const float* A = (src_sel == 0) ? Aext : (src_sel == 1 ? g_bufA : g_bufB);
    float* Cout = (dst_sel == 1) ? g_bufA : g_bufB;

    __shared__ __align__(16) float As[8][128];
    __shared__ __align__(16) float Bs[8][128];

    int tid = threadIdx.x;
    int tx = tid & 15;         // 0..15 -> N
    int ty = tid >> 4;         // 0..15 -> M
    int block_row = blockIdx.x * 128;

    // acc[m][j] holds channels {tx*8+2j, tx*8+2j+1} for row ty*8+m
    unsigned long long acc[8][4];
    #pragma unroll
    for (int m = 0; m < 8; m++)
        #pragma unroll
        for (int j = 0; j < 4; j++) acc[m][j] = 0ull;

    int a_row = tid >> 1;            // 0..127
    int a_col = (tid & 1) * 4;       // 0 or 4
    int b_row = tid >> 5;            // 0..7
    int b_col = (tid & 31) * 4;      // 0..124

    for (int k0 = 0; k0 < 128; k0 += 8) {
        int gr = block_row + a_row;
        float4 av = make_float4(0.f, 0.f, 0.f, 0.f);
        if (gr < M) av = *(const float4*)(A + (size_t)gr * 128 + k0 + a_col);
        As[a_col + 0][a_row] = av.x;
        As[a_col + 1][a_row] = av.y;
        As[a_col + 2][a_row] = av.z;
        As[a_col + 3][a_row] = av.w;
        float4 bv = *(const float4*)(W + (size_t)(k0 + b_row) * 128 + b_col);
        *(float4*)&Bs[b_row][b_col] = bv;
        __syncthreads();

        #pragma unroll
        for (int k = 0; k < 8; k++) {
            float4 rma = *(const float4*)&As[k][ty * 8];
            float4 rmb = *(const float4*)&As[k][ty * 8 + 4];
            // B pairs come pre-packed straight out of LDS (64-bit loads)
            ulonglong2 bp01 = *(const ulonglong2*)&Bs[k][tx * 8];
            ulonglong2 bp23 = *(const ulonglong2*)&Bs[k][tx * 8 + 4];
            unsigned long long bp[4] = {bp01.x, bp01.y, bp23.x, bp23.y};
            float rmv[8] = {rma.x, rma.y, rma.z, rma.w,
                            rmb.x, rmb.y, rmb.z, rmb.w};
            #pragma unroll
            for (int m = 0; m < 8; m++) {
                unsigned long long am = pack2(rmv[m]);
                #pragma unroll
                for (int j = 0; j < 4; j++)
                    ffma2(acc[m][j], am, bp[j]);
            }
        }
        __syncthreads();
    }

    #pragma unroll
    for (int m = 0; m < 8; m++) {
        int gr = block_row + ty * 8 + m;
        if (gr < M) {
            unsigned long long* cp =
                (unsigned long long*)(Cout + (size_t)gr * 128 + tx * 8);
            ulonglong2 lo = make_ulonglong2(acc[m][0], acc[m][1]);
            ulonglong2 hi = make_ulonglong2(acc[m][2], acc[m][3]);
            *(ulonglong2*)(cp + 0) = lo;
            *(ulonglong2*)(cp + 2) = hi;
        }
    }
}

// ---------------- Aggregation: out[i] = sum coef*xw[nbr] + dinv[i]^2*xw[i] + b
// warp per node; lane owns 4 channels (float4).

__global__ void __launch_bounds__(256)
agg_kernel(int src_sel, const float* __restrict__ bias,
           float* __restrict__ out, int n, int do_relu) {
    const float* xw = (src_sel == 1) ? g_bufA : g_bufB;
    int warp = (blockIdx.x * blockDim.x + threadIdx.x) >> 5;
    int lane = threadIdx.x & 31;
    if (warp >= n) return;
    int i = warp;

    const float4* xw4 = (const float4*)xw;
    float4 b4 = ((const float4*)bias)[lane];
    float di = g_dinv[i];
    float sc = di * di;

    float4 self = __ldg(&xw4[(size_t)i * 32 + lane]);
    float4 acc = make_float4(self.x * sc, self.y * sc, self.z * sc, self.w * sc);

    int s = g_off[i], e = g_off[i + 1];
    for (int j0 = s; j0 < e; j0 += 32) {
        int j = j0 + lane;
        int idx = 0;
        float cf = 0.0f;
        if (j < e) { idx = g_eidx[j]; cf = g_ecoef[j]; }
        int m = min(32, e - j0);
        #pragma unroll 4
        for (int t = 0; t < m; ++t) {
            int r = __shfl_sync(0xffffffffu, idx, t);
            float c = __shfl_sync(0xffffffffu, cf, t);
            float4 v = __ldg(&xw4[(size_t)r * 32 + lane]);
            acc.x = fmaf(c, v.x, acc.x);
            acc.y = fmaf(c, v.y, acc.y);
            acc.z = fmaf(c, v.z, acc.z);
            acc.w = fmaf(c, v.w, acc.w);
        }
    }

    acc.x += b4.x; acc.y += b4.y; acc.z += b4.z; acc.w += b4.w;
    if (do_relu) {
        acc.x = fmaxf(acc.x, 0.0f);
        acc.y = fmaxf(acc.y, 0.0f);
        acc.z = fmaxf(acc.z, 0.0f);
        acc.w = fmaxf(acc.w, 0.0f);
    }
    ((float4*)out)[(size_t)i * 32 + lane] = acc;
}

// ---------------- launch ------------------------------------------------------

extern "C" void kernel_launch(void* const* d_in, const int* in_sizes, int n_in,
                              void* d_out, int out_size) {
    const float* x   = (const float*)d_in[0];
    const int*   ei  = (const int*)d_in[1];
    const float* ew  = (const float*)d_in[2];
    const float* W1  = (const float*)d_in[3];
    const float* b1  = (const float*)d_in[4];
    const float* W2  = (const float*)d_in[5];
    const float* b2  = (const float*)d_in[6];
    const float* W3  = (const float*)d_in[7];
    const float* b3  = (const float*)d_in[8];
    float* out = (float*)d_out;

    int n = in_sizes[0] / CH;        // 100000
    int E = in_sizes[2];             // 1600000
    const int* row = ei;
    const int* col = ei + E;

    float* bufB = nullptr;
    cudaGetSymbolAddress((void**)&bufB, g_bufB);

    int tb = 256;
    int gn = (n + tb - 1) / tb;
    int ge = (E + tb - 1) / tb;
    int nb = (n + 1023) / 1024;
    int g_gemm = (n + 127) / 128;
    int g_agg = (n * 32 + tb - 1) / tb;

    // preprocessing: degrees + counts, parallel scan, dinv, CSR fill
    init_kernel<<<gn, tb>>>(n);
    deg_cnt_kernel<<<ge, tb>>>(row, col, ew, E);
    block_sum_kernel<<<nb, 1024>>>(n);
    scan_bsum_kernel<<<1, 32>>>(nb, n);
    scan_final_kernel<<<nb, 1024>>>(n);
    fill_kernel<<<ge, tb>>>(row, col, ew, E);

    // layer 1: bufA = x@W1 ; bufB = relu(Agg(bufA)+b1)
    gemm_kernel<<<g_gemm, tb>>>(x, 0, 1, W1, n);
    agg_kernel<<<g_agg, tb>>>(1, b1, bufB, n, 1);

    // layer 2: bufA = bufB@W2 ; bufB = relu(Agg(bufA)+b2)
    gemm_kernel<<<g_gemm, tb>>>(nullptr, 2, 1, W2, n);
    agg_kernel<<<g_agg, tb>>>(1, b2, bufB, n, 1);

    // layer 3: bufA = bufB@W3 ; out = Agg(bufA)+b3
    gemm_kernel<<<g_gemm, tb>>>(nullptr, 2, 1, W3, n);
    agg_kernel<<<g_agg, tb>>>(1, b3, out, n, 0);
}